// round 8
// baseline (speedup 1.0000x reference)
#include <cuda_runtime.h>
#include <cuda_bf16.h>
#include <math.h>
#include <stdint.h>

// ---------------- problem constants ----------------
#define BATCH   2
#define SEQLEN  2048
#define DMODEL  768
#define DINNER  1536
#define DSTATE  16
#define DCONV   4
#define DTRANK  48
#define XDBLW   (DTRANK + 2*DSTATE)   // 80
#define MROWS   (BATCH*SEQLEN)        // 4096
#define NPAIRS  (BATCH*DINNER)        // 3072
#define NCH     16
#define CHT     (SEQLEN/NCH)          // 128
#define SPLITK  4
#define XPSTRIDE ((size_t)MROWS * XDBLW)

// ---------------- scratch ----------------
__device__ float g_xz   [(size_t)MROWS * 2*DINNER];
__device__ float g_xc   [(size_t)MROWS * DINNER];
__device__ float g_xdbl [(size_t)MROWS * XDBLW];
__device__ float g_xp   [(size_t)SPLITK * MROWS * XDBLW];
__device__ float g_dt   [(size_t)MROWS * DINNER];
__device__ float g_y    [(size_t)MROWS * DINNER];
__device__ float g_q    [(size_t)MROWS * DINNER];
__device__ float g_aprod[(size_t)NPAIRS * NCH * DSTATE];
__device__ float g_hloc [(size_t)NPAIRS * NCH * DSTATE];
__device__ float g_h0   [(size_t)NPAIRS * NCH * DSTATE];

// ---------------- helpers ----------------
__device__ __forceinline__ float silu_f(float v)  { return v / (1.f + __expf(-v)); }
__device__ __forceinline__ float softplus_f(float v) { return v > 20.f ? v : log1pf(__expf(v)); }
__device__ __forceinline__ uint32_t f2tf32(float f) {
    uint32_t u; asm("cvt.rna.tf32.f32 %0, %1;" : "=r"(u) : "f"(f)); return u;
}
__device__ __forceinline__ void mma_tf32(float c[4], const uint32_t a[4], const uint32_t b[2]) {
    asm volatile(
        "mma.sync.aligned.m16n8k8.row.col.f32.tf32.tf32.f32 "
        "{%0,%1,%2,%3}, {%4,%5,%6,%7}, {%8,%9}, {%0,%1,%2,%3};\n"
        : "+f"(c[0]), "+f"(c[1]), "+f"(c[2]), "+f"(c[3])
        : "r"(a[0]), "r"(a[1]), "r"(a[2]), "r"(a[3]), "r"(b[0]), "r"(b[1]));
}
__device__ __forceinline__ int swz(int c) { return (c ^ (c >> 2)) & 31; }

// ---------------- mma.sync TF32 GEMM: C[M,N] = A[M,K] * B[N,K]^T ----------------
// Block 128x128, BK=16, 256 thr = 8 warps (2M x 4N), warp tile 64x32.
// Smem in per-lane MMA fragment layout (swizzled); double buffered, 1 sync/tile.
// Requires M % 128 == 0, K % (16*gridDim.z) == 0. N guarded.
// epi: 0 none, 1 softplus(acc+bias[n]), 2 acc+bias[n]
#define TBM 128
#define TBN 128
#define TBK 16

__global__ __launch_bounds__(256)
void gemm_tf32(const float* __restrict__ A, int lda,
               const float* __restrict__ B, int ldb,
               float* __restrict__ C, int ldc,
               int M, int N, int K,
               const float* __restrict__ bias, int epi,
               size_t splitStride)
{
    __shared__ float Af[2][2][8][128];
    __shared__ float Bf[2][2][16][64];

    const int tid  = threadIdx.x;
    const int warp = tid >> 5, lane = tid & 31;
    const int warpM = warp >> 2, warpN = warp & 3;

    const int rowBase = blockIdx.y * TBM;
    const int colBase = blockIdx.x * TBN;

    const int Ks = K / gridDim.z;
    A += (size_t)blockIdx.z * Ks;
    B += (size_t)blockIdx.z * Ks;
    C += (size_t)blockIdx.z * splitStride;

    const int lr  = tid >> 1;
    const int lks = tid & 1;
    const int lk  = lks * 8;

    const int wmi  = lr >> 4;
    const int wsel = (lr >> 3) & 1;
    const int wgid = lr & 7;
    const int wni  = lr >> 3;
    const int wbg  = lr & 7;

    float acc[4][4][4];
#pragma unroll
    for (int mi = 0; mi < 4; mi++)
#pragma unroll
        for (int ni = 0; ni < 4; ni++)
#pragma unroll
            for (int rr = 0; rr < 4; rr++) acc[mi][ni][rr] = 0.f;

    float4 pa0, pa1, pb0, pb1;
    {
        const float* ap = A + (size_t)(rowBase + lr) * lda + lk;
        pa0 = *(const float4*)(ap);
        pa1 = *(const float4*)(ap + 4);
        const int bn = colBase + lr;
        if (bn < N) {
            const float* bp = B + (size_t)bn * ldb + lk;
            pb0 = *(const float4*)(bp);
            pb1 = *(const float4*)(bp + 4);
        } else {
            pb0 = make_float4(0.f,0.f,0.f,0.f);
            pb1 = make_float4(0.f,0.f,0.f,0.f);
        }
    }

    const int ntiles = Ks / TBK;
    for (int t = 0; t < ntiles; t++) {
        const int buf = t & 1;
        {
            const float ea[8] = {pa0.x,pa0.y,pa0.z,pa0.w,pa1.x,pa1.y,pa1.z,pa1.w};
#pragma unroll
            for (int j = 0; j < 8; j++) {
                const int ch = swz(wgid * 4 + (j & 3));
                Af[buf][lks][wmi][ch * 4 + (j >> 2) * 2 + wsel] =
                    __uint_as_float(f2tf32(ea[j]));
            }
            const float eb[8] = {pb0.x,pb0.y,pb0.z,pb0.w,pb1.x,pb1.y,pb1.z,pb1.w};
#pragma unroll
            for (int j = 0; j < 4; j++) {
                const int ch = swz(wbg * 4 + j);
                Bf[buf][lks][wni][ch * 2 + 0] = __uint_as_float(f2tf32(eb[j]));
                Bf[buf][lks][wni][ch * 2 + 1] = __uint_as_float(f2tf32(eb[j + 4]));
            }
        }
        __syncthreads();

        if (t + 1 < ntiles) {
            const int k0 = (t + 1) * TBK;
            const float* apn = A + (size_t)(rowBase + lr) * lda + k0 + lk;
            pa0 = *(const float4*)(apn);
            pa1 = *(const float4*)(apn + 4);
            const int bn = colBase + lr;
            if (bn < N) {
                const float* bpn = B + (size_t)bn * ldb + k0 + lk;
                pb0 = *(const float4*)(bpn);
                pb1 = *(const float4*)(bpn + 4);
            } else {
                pb0 = make_float4(0.f,0.f,0.f,0.f);
                pb1 = make_float4(0.f,0.f,0.f,0.f);
            }
        }

#pragma unroll
        for (int ks = 0; ks < 2; ks++) {
            uint32_t af[4][4], bfr[4][2];
#pragma unroll
            for (int mi = 0; mi < 4; mi++) {
                const float4 v = *(const float4*)&Af[buf][ks][warpM*4 + mi][swz(lane)*4];
                af[mi][0] = __float_as_uint(v.x); af[mi][1] = __float_as_uint(v.y);
                af[mi][2] = __float_as_uint(v.z); af[mi][3] = __float_as_uint(v.w);
            }
#pragma unroll
            for (int ni = 0; ni < 4; ni++) {
                const float2 w = *(const float2*)&Bf[buf][ks][warpN*4 + ni][swz(lane)*2];
                bfr[ni][0] = __float_as_uint(w.x); bfr[ni][1] = __float_as_uint(w.y);
            }
#pragma unroll
            for (int mi = 0; mi < 4; mi++)
#pragma unroll
                for (int ni = 0; ni < 4; ni++)
                    mma_tf32(acc[mi][ni], af[mi], bfr[ni]);
        }
    }

    const int gid = lane >> 2, tg = lane & 3;
#pragma unroll
    for (int mi = 0; mi < 4; mi++) {
        const int r0 = rowBase + warpM * 64 + mi * 16 + gid;
#pragma unroll
        for (int ni = 0; ni < 4; ni++) {
            const int c = colBase + warpN * 32 + ni * 8 + 2 * tg;
            if (c < N) {
                float v0 = acc[mi][ni][0], v1 = acc[mi][ni][1];
                float v2 = acc[mi][ni][2], v3 = acc[mi][ni][3];
                if (epi == 1) {
                    const float b0 = bias[c], b1 = bias[c+1];
                    v0 = softplus_f(v0 + b0); v1 = softplus_f(v1 + b1);
                    v2 = softplus_f(v2 + b0); v3 = softplus_f(v3 + b1);
                } else if (epi == 2) {
                    const float b0 = bias[c], b1 = bias[c+1];
                    v0 += b0; v1 += b1; v2 += b0; v3 += b1;
                }
                *(float2*)(C + (size_t)r0       * ldc + c) = make_float2(v0, v1);
                *(float2*)(C + (size_t)(r0 + 8) * ldc + c) = make_float2(v2, v3);
            }
        }
    }
}

// ---------------- split-K reduction for x_proj ----------------
__global__ __launch_bounds__(256)
void reduce_xp(const float* __restrict__ part, float* __restrict__ xdbl)
{
    const int i = blockIdx.x * blockDim.x + threadIdx.x;
    if (i < (int)(MROWS * XDBLW)) {
        float s = part[i];
#pragma unroll
        for (int k = 1; k < SPLITK; k++) s += part[(size_t)k * XPSTRIDE + i];
        xdbl[i] = s;
    }
}

// ---------------- causal depthwise conv (width 4) + silu ----------------
__global__ __launch_bounds__(256)
void conv_silu_kernel(const float* __restrict__ xz,
                      const float* __restrict__ conv_w,
                      const float* __restrict__ conv_b,
                      float* __restrict__ xc)
{
    const int idx = blockIdx.x * blockDim.x + threadIdx.x;
    if (idx >= MROWS * DINNER) return;
    const int d = idx % DINNER;
    const int m = idx / DINNER;
    const int t = m % SEQLEN;

    float v = conv_b[d];
#pragma unroll
    for (int k = 0; k < DCONV; k++) {
        const int tt = t + k - (DCONV - 1);
        if (tt >= 0)
            v += conv_w[d * DCONV + k] * xz[(size_t)(m + tt - t) * (2 * DINNER) + d];
    }
    xc[idx] = silu_f(v);
}

// ---------------- chunked selective scan: thread-per-channel ----------------
#define SCB 128

__global__ __launch_bounds__(SCB)
void scan_phase1(const float* __restrict__ dt,
                 const float* __restrict__ xc,
                 const float* __restrict__ xdbl,
                 const float* __restrict__ A_log,
                 float* __restrict__ aprod_g,
                 float* __restrict__ hloc_g)
{
    __shared__ float Bsh[CHT][16];
    const int tid = threadIdx.x;
    const int dg = blockIdx.x % (DINNER / SCB);
    const int b  = (blockIdx.x / (DINNER / SCB)) % BATCH;
    const int c  =  blockIdx.x / ((DINNER / SCB) * BATCH);
    const int d  = dg * SCB + tid;
    const size_t m0 = (size_t)b * SEQLEN + c * CHT;

    for (int i = tid; i < CHT * 4; i += SCB) {
        const int r = i >> 2, qq = i & 3;
        *(float4*)&Bsh[r][qq * 4] =
            *(const float4*)&xdbl[(m0 + r) * XDBLW + DTRANK + qq * 4];
    }
    __syncthreads();

    float A[16];
    {
        const float4* ap = (const float4*)&A_log[(size_t)d * DSTATE];
#pragma unroll
        for (int i = 0; i < 4; i++) {
            const float4 v = ap[i];
            A[i*4+0] = -__expf(v.x); A[i*4+1] = -__expf(v.y);
            A[i*4+2] = -__expf(v.z); A[i*4+3] = -__expf(v.w);
        }
    }
    bool fast = true;
#pragma unroll
    for (int n = 0; n < 16; n++)
        fast = fast && (fabsf(A[n] + (float)(n + 1)) <= 1e-5f * (float)(n + 1));

    float h[16], ap[16];
#pragma unroll
    for (int n = 0; n < 16; n++) { h[n] = 0.f; ap[n] = 1.f; }

    if (fast) {
#pragma unroll 2
        for (int t = 0; t < CHT; t++) {
            const size_t m = m0 + t;
            const float dtv = dt[m * DINNER + d];
            const float du  = dtv * xc[m * DINNER + d];
            const float r1  = __expf(-dtv);
            float a = r1;
#pragma unroll
            for (int n = 0; n < 16; n++) {
                h[n] = a * h[n] + du * Bsh[t][n];
                ap[n] *= a;
                a *= r1;
            }
        }
    } else {
#pragma unroll 2
        for (int t = 0; t < CHT; t++) {
            const size_t m = m0 + t;
            const float dtv = dt[m * DINNER + d];
            const float du  = dtv * xc[m * DINNER + d];
#pragma unroll
            for (int n = 0; n < 16; n++) {
                const float a = __expf(dtv * A[n]);
                h[n] = a * h[n] + du * Bsh[t][n];
                ap[n] *= a;
            }
        }
    }

    const int bd = b * DINNER + d;
    float* po  = &aprod_g[((size_t)bd * NCH + c) * DSTATE];
    float* phh = &hloc_g [((size_t)bd * NCH + c) * DSTATE];
#pragma unroll
    for (int i = 0; i < 4; i++) {
        *(float4*)&po[i*4]  = make_float4(ap[i*4], ap[i*4+1], ap[i*4+2], ap[i*4+3]);
        *(float4*)&phh[i*4] = make_float4(h[i*4],  h[i*4+1],  h[i*4+2],  h[i*4+3]);
    }
}

__global__ __launch_bounds__(256)
void scan_phase2(const float* __restrict__ aprod_g,
                 const float* __restrict__ hloc_g,
                 float* __restrict__ h0_g)
{
    const int idx = blockIdx.x * blockDim.x + threadIdx.x;
    const int bd = idx >> 4;
    const int n  = idx & 15;
    if (bd >= NPAIRS) return;

    float h = 0.f;
#pragma unroll
    for (int c = 0; c < NCH; c++) {
        const size_t o = ((size_t)bd * NCH + c) * DSTATE + n;
        h0_g[o] = h;
        h = aprod_g[o] * h + hloc_g[o];
    }
}

// phase3 + combine fused: y = (scan + xc*D) * silu(z) * silu(q)
__global__ __launch_bounds__(SCB)
void scan_phase3(const float* __restrict__ dt,
                 const float* __restrict__ xc,
                 const float* __restrict__ xdbl,
                 const float* __restrict__ A_log,
                 const float* __restrict__ h0_g,
                 const float* __restrict__ xz,
                 const float* __restrict__ q,
                 const float* __restrict__ Dp,
                 float* __restrict__ y)
{
    __shared__ float Bsh[CHT][16];
    __shared__ float Csh[CHT][16];
    const int tid = threadIdx.x;
    const int dg = blockIdx.x % (DINNER / SCB);
    const int b  = (blockIdx.x / (DINNER / SCB)) % BATCH;
    const int c  =  blockIdx.x / ((DINNER / SCB) * BATCH);
    const int d  = dg * SCB + tid;
    const size_t m0 = (size_t)b * SEQLEN + c * CHT;

    for (int i = tid; i < CHT * 4; i += SCB) {
        const int r = i >> 2, qq = i & 3;
        *(float4*)&Bsh[r][qq * 4] =
            *(const float4*)&xdbl[(m0 + r) * XDBLW + DTRANK + qq * 4];
        *(float4*)&Csh[r][qq * 4] =
            *(const float4*)&xdbl[(m0 + r) * XDBLW + DTRANK + DSTATE + qq * 4];
    }
    __syncthreads();

    float A[16];
    {
        const float4* ap = (const float4*)&A_log[(size_t)d * DSTATE];
#pragma unroll
        for (int i = 0; i < 4; i++) {
            const float4 v = ap[i];
            A[i*4+0] = -__expf(v.x); A[i*4+1] = -__expf(v.y);
            A[i*4+2] = -__expf(v.z); A[i*4+3] = -__expf(v.w);
        }
    }
    bool fast = true;
#pragma unroll
    for (int n = 0; n < 16; n++)
        fast = fast && (fabsf(A[n] + (float)(n + 1)) <= 1e-5f * (float)(n + 1));

    const int bd = b * DINNER + d;
    const float Dv = Dp[d];
    float h[16];
    {
        const float4* hp = (const float4*)&h0_g[((size_t)bd * NCH + c) * DSTATE];
#pragma unroll
        for (int i = 0; i < 4; i++) {
            const float4 v = hp[i];
            h[i*4+0] = v.x; h[i*4+1] = v.y; h[i*4+2] = v.z; h[i*4+3] = v.w;
        }
    }

    if (fast) {
#pragma unroll 2
        for (int t = 0; t < CHT; t++) {
            const size_t m = m0 + t;
            const float dtv = dt[m * DINNER + d];
            const float xv  = xc[m * DINNER + d];
            const float du  = dtv * xv;
            const float r1  = __expf(-dtv);
            float a = r1, p = 0.f;
#pragma unroll
            for (int n = 0; n < 16; n++) {
                h[n] = a * h[n] + du * Bsh[t][n];
                p += h[n] * Csh[t][n];
                a *= r1;
            }
            const float zv = xz[m * (2 * DINNER) + DINNER + d];
            const float qv = q[m * DINNER + d];
            y[m * DINNER + d] = (p + xv * Dv) * silu_f(zv) * silu_f(qv);
        }
    } else {
#pragma unroll 2
        for (int t = 0; t < CHT; t++) {
            const size_t m = m0 + t;
            const float dtv = dt[m * DINNER + d];
            const float xv  = xc[m * DINNER + d];
            const float du  = dtv * xv;
            float p = 0.f;
#pragma unroll
            for (int n = 0; n < 16; n++) {
                const float a = __expf(dtv * A[n]);
                h[n] = a * h[n] + du * Bsh[t][n];
                p += h[n] * Csh[t][n];
            }
            const float zv = xz[m * (2 * DINNER) + DINNER + d];
            const float qv = q[m * DINNER + d];
            y[m * DINNER + d] = (p + xv * Dv) * silu_f(zv) * silu_f(qv);
        }
    }
}

// ---------------- launch ----------------
extern "C" void kernel_launch(void* const* d_in, const int* in_sizes, int n_in,
                              void* d_out, int out_size)
{
    const float* hidden    = (const float*)d_in[0];
    const float* query     = (const float*)d_in[1];
    const float* in_proj_w = (const float*)d_in[2];
    const float* conv_w    = (const float*)d_in[3];
    const float* conv_b    = (const float*)d_in[4];
    const float* x_proj_w  = (const float*)d_in[5];
    const float* dt_proj_w = (const float*)d_in[6];
    const float* dt_proj_b = (const float*)d_in[7];
    const float* A_log     = (const float*)d_in[8];
    const float* Dp        = (const float*)d_in[9];
    const float* query_w   = (const float*)d_in[10];
    const float* query_b   = (const float*)d_in[11];
    const float* out_proj_w= (const float*)d_in[12];
    float* out = (float*)d_out;

    float *xz, *xc, *xdbl, *xp, *dt, *y, *q, *aprod, *hloc, *h0;
    cudaGetSymbolAddress((void**)&xz,    g_xz);
    cudaGetSymbolAddress((void**)&xc,    g_xc);
    cudaGetSymbolAddress((void**)&xdbl,  g_xdbl);
    cudaGetSymbolAddress((void**)&xp,    g_xp);
    cudaGetSymbolAddress((void**)&dt,    g_dt);
    cudaGetSymbolAddress((void**)&y,     g_y);
    cudaGetSymbolAddress((void**)&q,     g_q);
    cudaGetSymbolAddress((void**)&aprod, g_aprod);
    cudaGetSymbolAddress((void**)&hloc,  g_hloc);
    cudaGetSymbolAddress((void**)&h0,    g_h0);

    const int elemN = MROWS * DINNER;
    const int elemBlocks = (elemN + 255) / 256;

    // 1) xz = hidden @ in_proj_w^T        (4096 x 3072, K=768)
    gemm_tf32<<<dim3(2 * DINNER / TBN, MROWS / TBM, 1), 256>>>(
        hidden, DMODEL, in_proj_w, DMODEL, xz, 2 * DINNER,
        MROWS, 2 * DINNER, DMODEL, nullptr, 0, 0);

    // 2) causal conv + silu
    conv_silu_kernel<<<elemBlocks, 256>>>(xz, conv_w, conv_b, xc);

    // 3) x_dbl = xc @ x_proj_w^T          (4096 x 80, K=1536) split-K=4
    gemm_tf32<<<dim3(1, MROWS / TBM, SPLITK), 256>>>(
        xc, DINNER, x_proj_w, DINNER, xp, XDBLW,
        MROWS, XDBLW, DINNER, nullptr, 0, XPSTRIDE);
    reduce_xp<<<(MROWS * XDBLW + 255) / 256, 256>>>(xp, xdbl);

    // 4) dt = softplus(x_dbl[:, :48] @ dt_proj_w^T + b)   (4096 x 1536, K=48)
    gemm_tf32<<<dim3(DINNER / TBN, MROWS / TBM, 1), 256>>>(
        xdbl, XDBLW, dt_proj_w, DTRANK, dt, DINNER,
        MROWS, DINNER, DTRANK, dt_proj_b, 1, 0);

    // 5) q = query @ query_w^T + query_b  (4096 x 1536, K=768)
    gemm_tf32<<<dim3(DINNER / TBN, MROWS / TBM, 1), 256>>>(
        query, DMODEL, query_w, DMODEL, q, DINNER,
        MROWS, DINNER, DMODEL, query_b, 2, 0);

    // 6) chunked selective scan (phase3 fused with gating)
    {
        const int nblk = (DINNER / SCB) * BATCH * NCH;   // 384
        scan_phase1<<<nblk, SCB>>>(dt, xc, xdbl, A_log, aprod, hloc);
        scan_phase2<<<(NPAIRS * DSTATE) / 256, 256>>>(aprod, hloc, h0);
        scan_phase3<<<nblk, SCB>>>(dt, xc, xdbl, A_log, h0, xz, q, Dp, y);
    }

    // 7) out = y @ out_proj_w^T           (4096 x 768, K=1536)
    gemm_tf32<<<dim3(DMODEL / TBN, MROWS / TBM, 1), 256>>>(
        y, DINNER, out_proj_w, DINNER, out, DMODEL,
        MROWS, DMODEL, DINNER, nullptr, 0, 0);
}

// round 9
// speedup vs baseline: 1.0289x; 1.0289x over previous
#include <cuda_runtime.h>
#include <cuda_bf16.h>
#include <math.h>
#include <stdint.h>

// ---------------- problem constants ----------------
#define BATCH   2
#define SEQLEN  2048
#define DMODEL  768
#define DINNER  1536
#define DSTATE  16
#define DCONV   4
#define DTRANK  48
#define XDBLW   (DTRANK + 2*DSTATE)   // 80
#define MROWS   (BATCH*SEQLEN)        // 4096
#define NPAIRS  (BATCH*DINNER)        // 3072
#define NCH     16
#define CHT     (SEQLEN/NCH)          // 128
#define SPLITK  4
#define XPSTRIDE ((size_t)MROWS * XDBLW)
#define OPSTRIDE ((size_t)MROWS * DMODEL)

// ---------------- scratch ----------------
__device__ float g_xz   [(size_t)MROWS * 2*DINNER];
__device__ float g_xc   [(size_t)MROWS * DINNER];
__device__ float g_xdbl [(size_t)MROWS * XDBLW];
__device__ float g_xp   [(size_t)SPLITK * MROWS * XDBLW];
__device__ float g_op   [(size_t)2 * MROWS * DMODEL];
__device__ float g_dt   [(size_t)MROWS * DINNER];
__device__ float g_y    [(size_t)MROWS * DINNER];
__device__ float g_q    [(size_t)MROWS * DINNER];
__device__ float g_aprod[(size_t)NPAIRS * NCH * DSTATE];
__device__ float g_hloc [(size_t)NPAIRS * NCH * DSTATE];
__device__ float g_h0   [(size_t)NPAIRS * NCH * DSTATE];

// ---------------- helpers ----------------
__device__ __forceinline__ float silu_f(float v)  { return v / (1.f + __expf(-v)); }
__device__ __forceinline__ float softplus_f(float v) { return v > 20.f ? v : log1pf(__expf(v)); }
__device__ __forceinline__ uint32_t f2tf32(float f) {
    uint32_t u; asm("cvt.rna.tf32.f32 %0, %1;" : "=r"(u) : "f"(f)); return u;
}
__device__ __forceinline__ void mma_tf32(float c[4], const uint32_t a[4], const uint32_t b[2]) {
    asm volatile(
        "mma.sync.aligned.m16n8k8.row.col.f32.tf32.tf32.f32 "
        "{%0,%1,%2,%3}, {%4,%5,%6,%7}, {%8,%9}, {%0,%1,%2,%3};\n"
        : "+f"(c[0]), "+f"(c[1]), "+f"(c[2]), "+f"(c[3])
        : "r"(a[0]), "r"(a[1]), "r"(a[2]), "r"(a[3]), "r"(b[0]), "r"(b[1]));
}
__device__ __forceinline__ int swz(int c) { return (c ^ (c >> 2)) & 31; }

// ---------------- mma.sync TF32 GEMM: C[M,N] = A[M,K] * B[N,K]^T ----------------
// Block 128x128, BK=16, 256 thr = 8 warps (2M x 4N), warp tile 64x32.
// Smem in per-lane MMA fragment layout (swizzled); double buffered, 1 sync/tile.
// Requires M % 128 == 0, K % (16*gridDim.z) == 0. N guarded.
// epi: 0 none, 1 softplus(acc+bias[n]), 2 acc+bias[n]
#define TBM 128
#define TBN 128
#define TBK 16

__global__ __launch_bounds__(256)
void gemm_tf32(const float* __restrict__ A, int lda,
               const float* __restrict__ B, int ldb,
               float* __restrict__ C, int ldc,
               int M, int N, int K,
               const float* __restrict__ bias, int epi,
               size_t splitStride)
{
    __shared__ float Af[2][2][8][128];
    __shared__ float Bf[2][2][16][64];

    const int tid  = threadIdx.x;
    const int warp = tid >> 5, lane = tid & 31;
    const int warpM = warp >> 2, warpN = warp & 3;

    const int rowBase = blockIdx.y * TBM;
    const int colBase = blockIdx.x * TBN;

    const int Ks = K / gridDim.z;
    A += (size_t)blockIdx.z * Ks;
    B += (size_t)blockIdx.z * Ks;
    C += (size_t)blockIdx.z * splitStride;

    const int lr  = tid >> 1;
    const int lks = tid & 1;
    const int lk  = lks * 8;

    const int wmi  = lr >> 4;
    const int wsel = (lr >> 3) & 1;
    const int wgid = lr & 7;
    const int wni  = lr >> 3;
    const int wbg  = lr & 7;

    float acc[4][4][4];
#pragma unroll
    for (int mi = 0; mi < 4; mi++)
#pragma unroll
        for (int ni = 0; ni < 4; ni++)
#pragma unroll
            for (int rr = 0; rr < 4; rr++) acc[mi][ni][rr] = 0.f;

    float4 pa0, pa1, pb0, pb1;
    {
        const float* ap = A + (size_t)(rowBase + lr) * lda + lk;
        pa0 = *(const float4*)(ap);
        pa1 = *(const float4*)(ap + 4);
        const int bn = colBase + lr;
        if (bn < N) {
            const float* bp = B + (size_t)bn * ldb + lk;
            pb0 = *(const float4*)(bp);
            pb1 = *(const float4*)(bp + 4);
        } else {
            pb0 = make_float4(0.f,0.f,0.f,0.f);
            pb1 = make_float4(0.f,0.f,0.f,0.f);
        }
    }

    const int ntiles = Ks / TBK;
    for (int t = 0; t < ntiles; t++) {
        const int buf = t & 1;
        {
            const float ea[8] = {pa0.x,pa0.y,pa0.z,pa0.w,pa1.x,pa1.y,pa1.z,pa1.w};
#pragma unroll
            for (int j = 0; j < 8; j++) {
                const int ch = swz(wgid * 4 + (j & 3));
                Af[buf][lks][wmi][ch * 4 + (j >> 2) * 2 + wsel] =
                    __uint_as_float(f2tf32(ea[j]));
            }
            const float eb[8] = {pb0.x,pb0.y,pb0.z,pb0.w,pb1.x,pb1.y,pb1.z,pb1.w};
#pragma unroll
            for (int j = 0; j < 4; j++) {
                const int ch = swz(wbg * 4 + j);
                Bf[buf][lks][wni][ch * 2 + 0] = __uint_as_float(f2tf32(eb[j]));
                Bf[buf][lks][wni][ch * 2 + 1] = __uint_as_float(f2tf32(eb[j + 4]));
            }
        }
        __syncthreads();

        if (t + 1 < ntiles) {
            const int k0 = (t + 1) * TBK;
            const float* apn = A + (size_t)(rowBase + lr) * lda + k0 + lk;
            pa0 = *(const float4*)(apn);
            pa1 = *(const float4*)(apn + 4);
            const int bn = colBase + lr;
            if (bn < N) {
                const float* bpn = B + (size_t)bn * ldb + k0 + lk;
                pb0 = *(const float4*)(bpn);
                pb1 = *(const float4*)(bpn + 4);
            } else {
                pb0 = make_float4(0.f,0.f,0.f,0.f);
                pb1 = make_float4(0.f,0.f,0.f,0.f);
            }
        }

#pragma unroll
        for (int ks = 0; ks < 2; ks++) {
            uint32_t af[4][4], bfr[4][2];
#pragma unroll
            for (int mi = 0; mi < 4; mi++) {
                const float4 v = *(const float4*)&Af[buf][ks][warpM*4 + mi][swz(lane)*4];
                af[mi][0] = __float_as_uint(v.x); af[mi][1] = __float_as_uint(v.y);
                af[mi][2] = __float_as_uint(v.z); af[mi][3] = __float_as_uint(v.w);
            }
#pragma unroll
            for (int ni = 0; ni < 4; ni++) {
                const float2 w = *(const float2*)&Bf[buf][ks][warpN*4 + ni][swz(lane)*2];
                bfr[ni][0] = __float_as_uint(w.x); bfr[ni][1] = __float_as_uint(w.y);
            }
#pragma unroll
            for (int mi = 0; mi < 4; mi++)
#pragma unroll
                for (int ni = 0; ni < 4; ni++)
                    mma_tf32(acc[mi][ni], af[mi], bfr[ni]);
        }
    }

    const int gid = lane >> 2, tg = lane & 3;
#pragma unroll
    for (int mi = 0; mi < 4; mi++) {
        const int r0 = rowBase + warpM * 64 + mi * 16 + gid;
#pragma unroll
        for (int ni = 0; ni < 4; ni++) {
            const int c = colBase + warpN * 32 + ni * 8 + 2 * tg;
            if (c < N) {
                float v0 = acc[mi][ni][0], v1 = acc[mi][ni][1];
                float v2 = acc[mi][ni][2], v3 = acc[mi][ni][3];
                if (epi == 1) {
                    const float b0 = bias[c], b1 = bias[c+1];
                    v0 = softplus_f(v0 + b0); v1 = softplus_f(v1 + b1);
                    v2 = softplus_f(v2 + b0); v3 = softplus_f(v3 + b1);
                } else if (epi == 2) {
                    const float b0 = bias[c], b1 = bias[c+1];
                    v0 += b0; v1 += b1; v2 += b0; v3 += b1;
                }
                *(float2*)(C + (size_t)r0       * ldc + c) = make_float2(v0, v1);
                *(float2*)(C + (size_t)(r0 + 8) * ldc + c) = make_float2(v2, v3);
            }
        }
    }
}

// ---------------- split-K reductions ----------------
__global__ __launch_bounds__(256)
void reduce_xp(const float* __restrict__ part, float* __restrict__ xdbl)
{
    const int i = blockIdx.x * blockDim.x + threadIdx.x;
    if (i < (int)(MROWS * XDBLW)) {
        float s = part[i];
#pragma unroll
        for (int k = 1; k < SPLITK; k++) s += part[(size_t)k * XPSTRIDE + i];
        xdbl[i] = s;
    }
}

__global__ __launch_bounds__(256)
void reduce_out(const float* __restrict__ part, float* __restrict__ out)
{
    const int i = blockIdx.x * blockDim.x + threadIdx.x;
    if (i < (int)(MROWS * DMODEL))
        out[i] = part[i] + part[OPSTRIDE + i];
}

// ---------------- causal depthwise conv (width 4) + silu ----------------
__global__ __launch_bounds__(256)
void conv_silu_kernel(const float* __restrict__ xz,
                      const float* __restrict__ conv_w,
                      const float* __restrict__ conv_b,
                      float* __restrict__ xc)
{
    const int idx = blockIdx.x * blockDim.x + threadIdx.x;
    if (idx >= MROWS * DINNER) return;
    const int d = idx % DINNER;
    const int m = idx / DINNER;
    const int t = m % SEQLEN;

    float v = conv_b[d];
#pragma unroll
    for (int k = 0; k < DCONV; k++) {
        const int tt = t + k - (DCONV - 1);
        if (tt >= 0)
            v += conv_w[d * DCONV + k] * xz[(size_t)(m + tt - t) * (2 * DINNER) + d];
    }
    xc[idx] = silu_f(v);
}

// ---------------- chunked selective scan: thread-per-channel ----------------
#define SCB 128

__global__ __launch_bounds__(SCB)
void scan_phase1(const float* __restrict__ dt,
                 const float* __restrict__ xc,
                 const float* __restrict__ xdbl,
                 const float* __restrict__ A_log,
                 float* __restrict__ aprod_g,
                 float* __restrict__ hloc_g)
{
    __shared__ float Bsh[CHT][16];
    const int tid = threadIdx.x;
    const int dg = blockIdx.x % (DINNER / SCB);
    const int b  = (blockIdx.x / (DINNER / SCB)) % BATCH;
    const int c  =  blockIdx.x / ((DINNER / SCB) * BATCH);
    const int d  = dg * SCB + tid;
    const size_t m0 = (size_t)b * SEQLEN + c * CHT;

    for (int i = tid; i < CHT * 4; i += SCB) {
        const int r = i >> 2, qq = i & 3;
        *(float4*)&Bsh[r][qq * 4] =
            *(const float4*)&xdbl[(m0 + r) * XDBLW + DTRANK + qq * 4];
    }
    __syncthreads();

    float A[16];
    {
        const float4* ap = (const float4*)&A_log[(size_t)d * DSTATE];
#pragma unroll
        for (int i = 0; i < 4; i++) {
            const float4 v = ap[i];
            A[i*4+0] = -__expf(v.x); A[i*4+1] = -__expf(v.y);
            A[i*4+2] = -__expf(v.z); A[i*4+3] = -__expf(v.w);
        }
    }
    bool fast = true;
#pragma unroll
    for (int n = 0; n < 16; n++)
        fast = fast && (fabsf(A[n] + (float)(n + 1)) <= 1e-5f * (float)(n + 1));

    float h[16], ap[16];
#pragma unroll
    for (int n = 0; n < 16; n++) { h[n] = 0.f; ap[n] = 1.f; }

    if (fast) {
#pragma unroll 2
        for (int t = 0; t < CHT; t++) {
            const size_t m = m0 + t;
            const float dtv = dt[m * DINNER + d];
            const float du  = dtv * xc[m * DINNER + d];
            const float r1  = __expf(-dtv);
            float a = r1;
#pragma unroll
            for (int n = 0; n < 16; n++) {
                h[n] = a * h[n] + du * Bsh[t][n];
                ap[n] *= a;
                a *= r1;
            }
        }
    } else {
#pragma unroll 2
        for (int t = 0; t < CHT; t++) {
            const size_t m = m0 + t;
            const float dtv = dt[m * DINNER + d];
            const float du  = dtv * xc[m * DINNER + d];
#pragma unroll
            for (int n = 0; n < 16; n++) {
                const float a = __expf(dtv * A[n]);
                h[n] = a * h[n] + du * Bsh[t][n];
                ap[n] *= a;
            }
        }
    }

    const int bd = b * DINNER + d;
    float* po  = &aprod_g[((size_t)bd * NCH + c) * DSTATE];
    float* phh = &hloc_g [((size_t)bd * NCH + c) * DSTATE];
#pragma unroll
    for (int i = 0; i < 4; i++) {
        *(float4*)&po[i*4]  = make_float4(ap[i*4], ap[i*4+1], ap[i*4+2], ap[i*4+3]);
        *(float4*)&phh[i*4] = make_float4(h[i*4],  h[i*4+1],  h[i*4+2],  h[i*4+3]);
    }
}

__global__ __launch_bounds__(256)
void scan_phase2(const float* __restrict__ aprod_g,
                 const float* __restrict__ hloc_g,
                 float* __restrict__ h0_g)
{
    const int idx = blockIdx.x * blockDim.x + threadIdx.x;
    const int bd = idx >> 4;
    const int n  = idx & 15;
    if (bd >= NPAIRS) return;

    float h = 0.f;
#pragma unroll
    for (int c = 0; c < NCH; c++) {
        const size_t o = ((size_t)bd * NCH + c) * DSTATE + n;
        h0_g[o] = h;
        h = aprod_g[o] * h + hloc_g[o];
    }
}

__global__ __launch_bounds__(SCB)
void scan_phase3(const float* __restrict__ dt,
                 const float* __restrict__ xc,
                 const float* __restrict__ xdbl,
                 const float* __restrict__ A_log,
                 const float* __restrict__ h0_g,
                 float* __restrict__ y)
{
    __shared__ float Bsh[CHT][16];
    __shared__ float Csh[CHT][16];
    const int tid = threadIdx.x;
    const int dg = blockIdx.x % (DINNER / SCB);
    const int b  = (blockIdx.x / (DINNER / SCB)) % BATCH;
    const int c  =  blockIdx.x / ((DINNER / SCB) * BATCH);
    const int d  = dg * SCB + tid;
    const size_t m0 = (size_t)b * SEQLEN + c * CHT;

    for (int i = tid; i < CHT * 4; i += SCB) {
        const int r = i >> 2, qq = i & 3;
        *(float4*)&Bsh[r][qq * 4] =
            *(const float4*)&xdbl[(m0 + r) * XDBLW + DTRANK + qq * 4];
        *(float4*)&Csh[r][qq * 4] =
            *(const float4*)&xdbl[(m0 + r) * XDBLW + DTRANK + DSTATE + qq * 4];
    }
    __syncthreads();

    float A[16];
    {
        const float4* ap = (const float4*)&A_log[(size_t)d * DSTATE];
#pragma unroll
        for (int i = 0; i < 4; i++) {
            const float4 v = ap[i];
            A[i*4+0] = -__expf(v.x); A[i*4+1] = -__expf(v.y);
            A[i*4+2] = -__expf(v.z); A[i*4+3] = -__expf(v.w);
        }
    }
    bool fast = true;
#pragma unroll
    for (int n = 0; n < 16; n++)
        fast = fast && (fabsf(A[n] + (float)(n + 1)) <= 1e-5f * (float)(n + 1));

    const int bd = b * DINNER + d;
    float h[16];
    {
        const float4* hp = (const float4*)&h0_g[((size_t)bd * NCH + c) * DSTATE];
#pragma unroll
        for (int i = 0; i < 4; i++) {
            const float4 v = hp[i];
            h[i*4+0] = v.x; h[i*4+1] = v.y; h[i*4+2] = v.z; h[i*4+3] = v.w;
        }
    }

    if (fast) {
#pragma unroll 2
        for (int t = 0; t < CHT; t++) {
            const size_t m = m0 + t;
            const float dtv = dt[m * DINNER + d];
            const float du  = dtv * xc[m * DINNER + d];
            const float r1  = __expf(-dtv);
            float a = r1, p = 0.f;
#pragma unroll
            for (int n = 0; n < 16; n++) {
                h[n] = a * h[n] + du * Bsh[t][n];
                p += h[n] * Csh[t][n];
                a *= r1;
            }
            y[m * DINNER + d] = p;
        }
    } else {
#pragma unroll 2
        for (int t = 0; t < CHT; t++) {
            const size_t m = m0 + t;
            const float dtv = dt[m * DINNER + d];
            const float du  = dtv * xc[m * DINNER + d];
            float p = 0.f;
#pragma unroll
            for (int n = 0; n < 16; n++) {
                const float a = __expf(dtv * A[n]);
                h[n] = a * h[n] + du * Bsh[t][n];
                p += h[n] * Csh[t][n];
            }
            y[m * DINNER + d] = p;
        }
    }
}

// ---------------- combine ----------------
__global__ __launch_bounds__(256)
void combine_kernel(float* __restrict__ y,
                    const float* __restrict__ xc,
                    const float* __restrict__ xz,
                    const float* __restrict__ q,
                    const float* __restrict__ Dp)
{
    const int idx = blockIdx.x * blockDim.x + threadIdx.x;
    if (idx >= MROWS * DINNER) return;
    const int d = idx % DINNER;
    const int m = idx / DINNER;
    const float zv = xz[(size_t)m * (2 * DINNER) + DINNER + d];
    const float qv = q[idx];
    y[idx] = (y[idx] + xc[idx] * Dp[d]) * silu_f(zv) * silu_f(qv);
}

// ---------------- launch ----------------
extern "C" void kernel_launch(void* const* d_in, const int* in_sizes, int n_in,
                              void* d_out, int out_size)
{
    const float* hidden    = (const float*)d_in[0];
    const float* query     = (const float*)d_in[1];
    const float* in_proj_w = (const float*)d_in[2];
    const float* conv_w    = (const float*)d_in[3];
    const float* conv_b    = (const float*)d_in[4];
    const float* x_proj_w  = (const float*)d_in[5];
    const float* dt_proj_w = (const float*)d_in[6];
    const float* dt_proj_b = (const float*)d_in[7];
    const float* A_log     = (const float*)d_in[8];
    const float* Dp        = (const float*)d_in[9];
    const float* query_w   = (const float*)d_in[10];
    const float* query_b   = (const float*)d_in[11];
    const float* out_proj_w= (const float*)d_in[12];
    float* out = (float*)d_out;

    float *xz, *xc, *xdbl, *xp, *op, *dt, *y, *q, *aprod, *hloc, *h0;
    cudaGetSymbolAddress((void**)&xz,    g_xz);
    cudaGetSymbolAddress((void**)&xc,    g_xc);
    cudaGetSymbolAddress((void**)&xdbl,  g_xdbl);
    cudaGetSymbolAddress((void**)&xp,    g_xp);
    cudaGetSymbolAddress((void**)&op,    g_op);
    cudaGetSymbolAddress((void**)&dt,    g_dt);
    cudaGetSymbolAddress((void**)&y,     g_y);
    cudaGetSymbolAddress((void**)&q,     g_q);
    cudaGetSymbolAddress((void**)&aprod, g_aprod);
    cudaGetSymbolAddress((void**)&hloc,  g_hloc);
    cudaGetSymbolAddress((void**)&h0,    g_h0);

    const int elemN = MROWS * DINNER;
    const int elemBlocks = (elemN + 255) / 256;

    // 1) xz = hidden @ in_proj_w^T        (4096 x 3072, K=768)
    gemm_tf32<<<dim3(2 * DINNER / TBN, MROWS / TBM, 1), 256>>>(
        hidden, DMODEL, in_proj_w, DMODEL, xz, 2 * DINNER,
        MROWS, 2 * DINNER, DMODEL, nullptr, 0, 0);

    // 2) causal conv + silu
    conv_silu_kernel<<<elemBlocks, 256>>>(xz, conv_w, conv_b, xc);

    // 3) x_dbl = xc @ x_proj_w^T          (4096 x 80, K=1536) split-K=4
    gemm_tf32<<<dim3(1, MROWS / TBM, SPLITK), 256>>>(
        xc, DINNER, x_proj_w, DINNER, xp, XDBLW,
        MROWS, XDBLW, DINNER, nullptr, 0, XPSTRIDE);
    reduce_xp<<<(MROWS * XDBLW + 255) / 256, 256>>>(xp, xdbl);

    // 4) dt = softplus(x_dbl[:, :48] @ dt_proj_w^T + b)   (4096 x 1536, K=48)
    gemm_tf32<<<dim3(DINNER / TBN, MROWS / TBM, 1), 256>>>(
        xdbl, XDBLW, dt_proj_w, DTRANK, dt, DINNER,
        MROWS, DINNER, DTRANK, dt_proj_b, 1, 0);

    // 5) q = query @ query_w^T + query_b  (4096 x 1536, K=768)
    gemm_tf32<<<dim3(DINNER / TBN, MROWS / TBM, 1), 256>>>(
        query, DMODEL, query_w, DMODEL, q, DINNER,
        MROWS, DINNER, DMODEL, query_b, 2, 0);

    // 6) chunked selective scan
    {
        const int nblk = (DINNER / SCB) * BATCH * NCH;   // 384
        scan_phase1<<<nblk, SCB>>>(dt, xc, xdbl, A_log, aprod, hloc);
        scan_phase2<<<(NPAIRS * DSTATE) / 256, 256>>>(aprod, hloc, h0);
        scan_phase3<<<nblk, SCB>>>(dt, xc, xdbl, A_log, h0, y);
    }

    // 7) combine gates
    combine_kernel<<<elemBlocks, 256>>>(y, xc, xz, q, Dp);

    // 8) out = y @ out_proj_w^T           (4096 x 768, K=1536) split-K=2
    gemm_tf32<<<dim3(DMODEL / TBN, MROWS / TBM, 2), 256>>>(
        y, DINNER, out_proj_w, DINNER, op, DMODEL,
        MROWS, DMODEL, DINNER, nullptr, 0, OPSTRIDE);
    reduce_out<<<(MROWS * DMODEL + 255) / 256, 256>>>(op, out);
}

// round 10
// speedup vs baseline: 1.0892x; 1.0586x over previous
#include <cuda_runtime.h>
#include <cuda_bf16.h>
#include <math.h>
#include <stdint.h>

// ---------------- problem constants ----------------
#define BATCH   2
#define SEQLEN  2048
#define DMODEL  768
#define DINNER  1536
#define DSTATE  16
#define DCONV   4
#define DTRANK  48
#define XDBLW   (DTRANK + 2*DSTATE)   // 80
#define MROWS   (BATCH*SEQLEN)        // 4096
#define NPAIRS  (BATCH*DINNER)        // 3072
#define NCH     32
#define CHT     (SEQLEN/NCH)          // 64
#define SPLITK  4
#define XPSTRIDE ((size_t)MROWS * XDBLW)

// ---------------- scratch ----------------
__device__ float g_xz   [(size_t)MROWS * 2*DINNER];
__device__ float g_xc   [(size_t)MROWS * DINNER];
__device__ float g_xdbl [(size_t)MROWS * XDBLW];
__device__ float g_xp   [(size_t)SPLITK * MROWS * XDBLW];
__device__ float g_dt   [(size_t)MROWS * DINNER];
__device__ float g_y    [(size_t)MROWS * DINNER];
__device__ float g_q    [(size_t)MROWS * DINNER];
__device__ float g_aprod[(size_t)NPAIRS * NCH * DSTATE];
__device__ float g_hloc [(size_t)NPAIRS * NCH * DSTATE];
__device__ float g_h0   [(size_t)NPAIRS * NCH * DSTATE];

// ---------------- helpers ----------------
__device__ __forceinline__ float silu_f(float v)  { return v / (1.f + __expf(-v)); }
__device__ __forceinline__ float softplus_f(float v) { return v > 20.f ? v : log1pf(__expf(v)); }
__device__ __forceinline__ uint32_t f2tf32(float f) {
    uint32_t u; asm("cvt.rna.tf32.f32 %0, %1;" : "=r"(u) : "f"(f)); return u;
}
__device__ __forceinline__ void mma_tf32(float c[4], const uint32_t a[4], const uint32_t b[2]) {
    asm volatile(
        "mma.sync.aligned.m16n8k8.row.col.f32.tf32.tf32.f32 "
        "{%0,%1,%2,%3}, {%4,%5,%6,%7}, {%8,%9}, {%0,%1,%2,%3};\n"
        : "+f"(c[0]), "+f"(c[1]), "+f"(c[2]), "+f"(c[3])
        : "r"(a[0]), "r"(a[1]), "r"(a[2]), "r"(a[3]), "r"(b[0]), "r"(b[1]));
}
__device__ __forceinline__ int swz(int c) { return (c ^ (c >> 2)) & 31; }

// ---------------- mma.sync TF32 GEMM: C[M,N] = A[M,K] * B[N,K]^T ----------------
#define TBM 128
#define TBN 128
#define TBK 16

__global__ __launch_bounds__(256)
void gemm_tf32(const float* __restrict__ A, int lda,
               const float* __restrict__ B, int ldb,
               float* __restrict__ C, int ldc,
               int M, int N, int K,
               const float* __restrict__ bias, int epi,
               size_t splitStride)
{
    __shared__ float Af[2][2][8][128];
    __shared__ float Bf[2][2][16][64];

    const int tid  = threadIdx.x;
    const int warp = tid >> 5, lane = tid & 31;
    const int warpM = warp >> 2, warpN = warp & 3;

    const int rowBase = blockIdx.y * TBM;
    const int colBase = blockIdx.x * TBN;

    const int Ks = K / gridDim.z;
    A += (size_t)blockIdx.z * Ks;
    B += (size_t)blockIdx.z * Ks;
    C += (size_t)blockIdx.z * splitStride;

    const int lr  = tid >> 1;
    const int lks = tid & 1;
    const int lk  = lks * 8;

    const int wmi  = lr >> 4;
    const int wsel = (lr >> 3) & 1;
    const int wgid = lr & 7;
    const int wni  = lr >> 3;
    const int wbg  = lr & 7;

    float acc[4][4][4];
#pragma unroll
    for (int mi = 0; mi < 4; mi++)
#pragma unroll
        for (int ni = 0; ni < 4; ni++)
#pragma unroll
            for (int rr = 0; rr < 4; rr++) acc[mi][ni][rr] = 0.f;

    float4 pa0, pa1, pb0, pb1;
    {
        const float* ap = A + (size_t)(rowBase + lr) * lda + lk;
        pa0 = *(const float4*)(ap);
        pa1 = *(const float4*)(ap + 4);
        const int bn = colBase + lr;
        if (bn < N) {
            const float* bp = B + (size_t)bn * ldb + lk;
            pb0 = *(const float4*)(bp);
            pb1 = *(const float4*)(bp + 4);
        } else {
            pb0 = make_float4(0.f,0.f,0.f,0.f);
            pb1 = make_float4(0.f,0.f,0.f,0.f);
        }
    }

    const int ntiles = Ks / TBK;
    for (int t = 0; t < ntiles; t++) {
        const int buf = t & 1;
        {
            const float ea[8] = {pa0.x,pa0.y,pa0.z,pa0.w,pa1.x,pa1.y,pa1.z,pa1.w};
#pragma unroll
            for (int j = 0; j < 8; j++) {
                const int ch = swz(wgid * 4 + (j & 3));
                Af[buf][lks][wmi][ch * 4 + (j >> 2) * 2 + wsel] =
                    __uint_as_float(f2tf32(ea[j]));
            }
            const float eb[8] = {pb0.x,pb0.y,pb0.z,pb0.w,pb1.x,pb1.y,pb1.z,pb1.w};
#pragma unroll
            for (int j = 0; j < 4; j++) {
                const int ch = swz(wbg * 4 + j);
                Bf[buf][lks][wni][ch * 2 + 0] = __uint_as_float(f2tf32(eb[j]));
                Bf[buf][lks][wni][ch * 2 + 1] = __uint_as_float(f2tf32(eb[j + 4]));
            }
        }
        __syncthreads();

        if (t + 1 < ntiles) {
            const int k0 = (t + 1) * TBK;
            const float* apn = A + (size_t)(rowBase + lr) * lda + k0 + lk;
            pa0 = *(const float4*)(apn);
            pa1 = *(const float4*)(apn + 4);
            const int bn = colBase + lr;
            if (bn < N) {
                const float* bpn = B + (size_t)bn * ldb + k0 + lk;
                pb0 = *(const float4*)(bpn);
                pb1 = *(const float4*)(bpn + 4);
            } else {
                pb0 = make_float4(0.f,0.f,0.f,0.f);
                pb1 = make_float4(0.f,0.f,0.f,0.f);
            }
        }

#pragma unroll
        for (int ks = 0; ks < 2; ks++) {
            uint32_t af[4][4], bfr[4][2];
#pragma unroll
            for (int mi = 0; mi < 4; mi++) {
                const float4 v = *(const float4*)&Af[buf][ks][warpM*4 + mi][swz(lane)*4];
                af[mi][0] = __float_as_uint(v.x); af[mi][1] = __float_as_uint(v.y);
                af[mi][2] = __float_as_uint(v.z); af[mi][3] = __float_as_uint(v.w);
            }
#pragma unroll
            for (int ni = 0; ni < 4; ni++) {
                const float2 w = *(const float2*)&Bf[buf][ks][warpN*4 + ni][swz(lane)*2];
                bfr[ni][0] = __float_as_uint(w.x); bfr[ni][1] = __float_as_uint(w.y);
            }
#pragma unroll
            for (int mi = 0; mi < 4; mi++)
#pragma unroll
                for (int ni = 0; ni < 4; ni++)
                    mma_tf32(acc[mi][ni], af[mi], bfr[ni]);
        }
    }

    const int gid = lane >> 2, tg = lane & 3;
#pragma unroll
    for (int mi = 0; mi < 4; mi++) {
        const int r0 = rowBase + warpM * 64 + mi * 16 + gid;
#pragma unroll
        for (int ni = 0; ni < 4; ni++) {
            const int c = colBase + warpN * 32 + ni * 8 + 2 * tg;
            if (c < N) {
                float v0 = acc[mi][ni][0], v1 = acc[mi][ni][1];
                float v2 = acc[mi][ni][2], v3 = acc[mi][ni][3];
                if (epi == 1) {
                    const float b0 = bias[c], b1 = bias[c+1];
                    v0 = softplus_f(v0 + b0); v1 = softplus_f(v1 + b1);
                    v2 = softplus_f(v2 + b0); v3 = softplus_f(v3 + b1);
                } else if (epi == 2) {
                    const float b0 = bias[c], b1 = bias[c+1];
                    v0 += b0; v1 += b1; v2 += b0; v3 += b1;
                }
                *(float2*)(C + (size_t)r0       * ldc + c) = make_float2(v0, v1);
                *(float2*)(C + (size_t)(r0 + 8) * ldc + c) = make_float2(v2, v3);
            }
        }
    }
}

// ---------------- split-K reduction for x_proj ----------------
__global__ __launch_bounds__(256)
void reduce_xp(const float* __restrict__ part, float* __restrict__ xdbl)
{
    const int i = blockIdx.x * blockDim.x + threadIdx.x;
    if (i < (int)(MROWS * XDBLW)) {
        float s = part[i];
#pragma unroll
        for (int k = 1; k < SPLITK; k++) s += part[(size_t)k * XPSTRIDE + i];
        xdbl[i] = s;
    }
}

// ---------------- causal depthwise conv (width 4) + silu ----------------
__global__ __launch_bounds__(256)
void conv_silu_kernel(const float* __restrict__ xz,
                      const float* __restrict__ conv_w,
                      const float* __restrict__ conv_b,
                      float* __restrict__ xc)
{
    const int idx = blockIdx.x * blockDim.x + threadIdx.x;
    if (idx >= MROWS * DINNER) return;
    const int d = idx % DINNER;
    const int m = idx / DINNER;
    const int t = m % SEQLEN;

    float v = conv_b[d];
#pragma unroll
    for (int k = 0; k < DCONV; k++) {
        const int tt = t + k - (DCONV - 1);
        if (tt >= 0)
            v += conv_w[d * DCONV + k] * xz[(size_t)(m + tt - t) * (2 * DINNER) + d];
    }
    xc[idx] = silu_f(v);
}

// ---------------- chunked selective scan: thread-per-channel, ILP-optimized ----------------
#define SCB 128

__global__ __launch_bounds__(SCB)
void scan_phase1(const float* __restrict__ dt,
                 const float* __restrict__ xc,
                 const float* __restrict__ xdbl,
                 const float* __restrict__ A_log,
                 float* __restrict__ aprod_g,
                 float* __restrict__ hloc_g)
{
    __shared__ float Bsh[CHT][16];
    const int tid = threadIdx.x;
    const int dg = blockIdx.x % (DINNER / SCB);
    const int b  = (blockIdx.x / (DINNER / SCB)) % BATCH;
    const int c  =  blockIdx.x / ((DINNER / SCB) * BATCH);
    const int d  = dg * SCB + tid;
    const size_t m0 = (size_t)b * SEQLEN + c * CHT;

    for (int i = tid; i < CHT * 4; i += SCB) {
        const int r = i >> 2, qq = i & 3;
        *(float4*)&Bsh[r][qq * 4] =
            *(const float4*)&xdbl[(m0 + r) * XDBLW + DTRANK + qq * 4];
    }
    __syncthreads();

    float A[16];
    {
        const float4* ap = (const float4*)&A_log[(size_t)d * DSTATE];
#pragma unroll
        for (int i = 0; i < 4; i++) {
            const float4 v = ap[i];
            A[i*4+0] = -__expf(v.x); A[i*4+1] = -__expf(v.y);
            A[i*4+2] = -__expf(v.z); A[i*4+3] = -__expf(v.w);
        }
    }
    bool fast = true;
#pragma unroll
    for (int n = 0; n < 16; n++)
        fast = fast && (fabsf(A[n] + (float)(n + 1)) <= 1e-5f * (float)(n + 1));

    float h[16];
#pragma unroll
    for (int n = 0; n < 16; n++) h[n] = 0.f;
    float ap16[16];

    if (fast) {
        float sdt = 0.f;
#pragma unroll 2
        for (int t = 0; t < CHT; t++) {
            const size_t m = m0 + t;
            const float dtv = dt[m * DINNER + d];
            const float du  = dtv * xc[m * DINNER + d];
            sdt += dtv;
            const float r1 = __expf(-dtv);
            float pw[17];
            pw[1] = r1;
#pragma unroll
            for (int n = 2; n <= 16; n++) pw[n] = pw[n >> 1] * pw[n - (n >> 1)];
#pragma unroll
            for (int n = 0; n < 16; n++)
                h[n] = pw[n + 1] * h[n] + du * Bsh[t][n];
        }
        const float rt_ = __expf(-sdt);
        float pw[17];
        pw[1] = rt_;
#pragma unroll
        for (int n = 2; n <= 16; n++) pw[n] = pw[n >> 1] * pw[n - (n >> 1)];
#pragma unroll
        for (int n = 0; n < 16; n++) ap16[n] = pw[n + 1];
    } else {
#pragma unroll
        for (int n = 0; n < 16; n++) ap16[n] = 1.f;
#pragma unroll 2
        for (int t = 0; t < CHT; t++) {
            const size_t m = m0 + t;
            const float dtv = dt[m * DINNER + d];
            const float du  = dtv * xc[m * DINNER + d];
#pragma unroll
            for (int n = 0; n < 16; n++) {
                const float a = __expf(dtv * A[n]);
                h[n] = a * h[n] + du * Bsh[t][n];
                ap16[n] *= a;
            }
        }
    }

    const int bd = b * DINNER + d;
    float* po  = &aprod_g[((size_t)bd * NCH + c) * DSTATE];
    float* phh = &hloc_g [((size_t)bd * NCH + c) * DSTATE];
#pragma unroll
    for (int i = 0; i < 4; i++) {
        *(float4*)&po[i*4]  = make_float4(ap16[i*4], ap16[i*4+1], ap16[i*4+2], ap16[i*4+3]);
        *(float4*)&phh[i*4] = make_float4(h[i*4],    h[i*4+1],    h[i*4+2],    h[i*4+3]);
    }
}

__global__ __launch_bounds__(256)
void scan_phase2(const float* __restrict__ aprod_g,
                 const float* __restrict__ hloc_g,
                 float* __restrict__ h0_g)
{
    const int idx = blockIdx.x * blockDim.x + threadIdx.x;
    const int bd = idx >> 4;
    const int n  = idx & 15;
    if (bd >= NPAIRS) return;

    float h = 0.f;
#pragma unroll
    for (int c = 0; c < NCH; c++) {
        const size_t o = ((size_t)bd * NCH + c) * DSTATE + n;
        h0_g[o] = h;
        h = aprod_g[o] * h + hloc_g[o];
    }
}

__global__ __launch_bounds__(SCB)
void scan_phase3(const float* __restrict__ dt,
                 const float* __restrict__ xc,
                 const float* __restrict__ xdbl,
                 const float* __restrict__ A_log,
                 const float* __restrict__ h0_g,
                 float* __restrict__ y)
{
    __shared__ float Bsh[CHT][16];
    __shared__ float Csh[CHT][16];
    const int tid = threadIdx.x;
    const int dg = blockIdx.x % (DINNER / SCB);
    const int b  = (blockIdx.x / (DINNER / SCB)) % BATCH;
    const int c  =  blockIdx.x / ((DINNER / SCB) * BATCH);
    const int d  = dg * SCB + tid;
    const size_t m0 = (size_t)b * SEQLEN + c * CHT;

    for (int i = tid; i < CHT * 4; i += SCB) {
        const int r = i >> 2, qq = i & 3;
        *(float4*)&Bsh[r][qq * 4] =
            *(const float4*)&xdbl[(m0 + r) * XDBLW + DTRANK + qq * 4];
        *(float4*)&Csh[r][qq * 4] =
            *(const float4*)&xdbl[(m0 + r) * XDBLW + DTRANK + DSTATE + qq * 4];
    }
    __syncthreads();

    float A[16];
    {
        const float4* ap = (const float4*)&A_log[(size_t)d * DSTATE];
#pragma unroll
        for (int i = 0; i < 4; i++) {
            const float4 v = ap[i];
            A[i*4+0] = -__expf(v.x); A[i*4+1] = -__expf(v.y);
            A[i*4+2] = -__expf(v.z); A[i*4+3] = -__expf(v.w);
        }
    }
    bool fast = true;
#pragma unroll
    for (int n = 0; n < 16; n++)
        fast = fast && (fabsf(A[n] + (float)(n + 1)) <= 1e-5f * (float)(n + 1));

    const int bd = b * DINNER + d;
    float h[16];
    {
        const float4* hp = (const float4*)&h0_g[((size_t)bd * NCH + c) * DSTATE];
#pragma unroll
        for (int i = 0; i < 4; i++) {
            const float4 v = hp[i];
            h[i*4+0] = v.x; h[i*4+1] = v.y; h[i*4+2] = v.z; h[i*4+3] = v.w;
        }
    }

    if (fast) {
#pragma unroll 2
        for (int t = 0; t < CHT; t++) {
            const size_t m = m0 + t;
            const float dtv = dt[m * DINNER + d];
            const float du  = dtv * xc[m * DINNER + d];
            const float r1  = __expf(-dtv);
            float pw[17];
            pw[1] = r1;
#pragma unroll
            for (int n = 2; n <= 16; n++) pw[n] = pw[n >> 1] * pw[n - (n >> 1)];
            float e[16];
#pragma unroll
            for (int n = 0; n < 16; n++) {
                h[n] = pw[n + 1] * h[n] + du * Bsh[t][n];
                e[n] = h[n] * Csh[t][n];
            }
#pragma unroll
            for (int st = 1; st < 16; st <<= 1)
#pragma unroll
                for (int n = 0; n < 16; n += 2 * st) e[n] += e[n + st];
            y[m * DINNER + d] = e[0];
        }
    } else {
#pragma unroll 2
        for (int t = 0; t < CHT; t++) {
            const size_t m = m0 + t;
            const float dtv = dt[m * DINNER + d];
            const float du  = dtv * xc[m * DINNER + d];
            float e[16];
#pragma unroll
            for (int n = 0; n < 16; n++) {
                const float a = __expf(dtv * A[n]);
                h[n] = a * h[n] + du * Bsh[t][n];
                e[n] = h[n] * Csh[t][n];
            }
#pragma unroll
            for (int st = 1; st < 16; st <<= 1)
#pragma unroll
                for (int n = 0; n < 16; n += 2 * st) e[n] += e[n + st];
            y[m * DINNER + d] = e[0];
        }
    }
}

// ---------------- combine ----------------
__global__ __launch_bounds__(256)
void combine_kernel(float* __restrict__ y,
                    const float* __restrict__ xc,
                    const float* __restrict__ xz,
                    const float* __restrict__ q,
                    const float* __restrict__ Dp)
{
    const int idx = blockIdx.x * blockDim.x + threadIdx.x;
    if (idx >= MROWS * DINNER) return;
    const int d = idx % DINNER;
    const int m = idx / DINNER;
    const float zv = xz[(size_t)m * (2 * DINNER) + DINNER + d];
    const float qv = q[idx];
    y[idx] = (y[idx] + xc[idx] * Dp[d]) * silu_f(zv) * silu_f(qv);
}

// ---------------- launch ----------------
extern "C" void kernel_launch(void* const* d_in, const int* in_sizes, int n_in,
                              void* d_out, int out_size)
{
    const float* hidden    = (const float*)d_in[0];
    const float* query     = (const float*)d_in[1];
    const float* in_proj_w = (const float*)d_in[2];
    const float* conv_w    = (const float*)d_in[3];
    const float* conv_b    = (const float*)d_in[4];
    const float* x_proj_w  = (const float*)d_in[5];
    const float* dt_proj_w = (const float*)d_in[6];
    const float* dt_proj_b = (const float*)d_in[7];
    const float* A_log     = (const float*)d_in[8];
    const float* Dp        = (const float*)d_in[9];
    const float* query_w   = (const float*)d_in[10];
    const float* query_b   = (const float*)d_in[11];
    const float* out_proj_w= (const float*)d_in[12];
    float* out = (float*)d_out;

    float *xz, *xc, *xdbl, *xp, *dt, *y, *q, *aprod, *hloc, *h0;
    cudaGetSymbolAddress((void**)&xz,    g_xz);
    cudaGetSymbolAddress((void**)&xc,    g_xc);
    cudaGetSymbolAddress((void**)&xdbl,  g_xdbl);
    cudaGetSymbolAddress((void**)&xp,    g_xp);
    cudaGetSymbolAddress((void**)&dt,    g_dt);
    cudaGetSymbolAddress((void**)&y,     g_y);
    cudaGetSymbolAddress((void**)&q,     g_q);
    cudaGetSymbolAddress((void**)&aprod, g_aprod);
    cudaGetSymbolAddress((void**)&hloc,  g_hloc);
    cudaGetSymbolAddress((void**)&h0,    g_h0);

    const int elemN = MROWS * DINNER;
    const int elemBlocks = (elemN + 255) / 256;

    // 1) xz = hidden @ in_proj_w^T        (4096 x 3072, K=768)
    gemm_tf32<<<dim3(2 * DINNER / TBN, MROWS / TBM, 1), 256>>>(
        hidden, DMODEL, in_proj_w, DMODEL, xz, 2 * DINNER,
        MROWS, 2 * DINNER, DMODEL, nullptr, 0, 0);

    // 2) causal conv + silu
    conv_silu_kernel<<<elemBlocks, 256>>>(xz, conv_w, conv_b, xc);

    // 3) x_dbl = xc @ x_proj_w^T          (4096 x 80, K=1536) split-K=4
    gemm_tf32<<<dim3(1, MROWS / TBM, SPLITK), 256>>>(
        xc, DINNER, x_proj_w, DINNER, xp, XDBLW,
        MROWS, XDBLW, DINNER, nullptr, 0, XPSTRIDE);
    reduce_xp<<<(MROWS * XDBLW + 255) / 256, 256>>>(xp, xdbl);

    // 4) dt = softplus(x_dbl[:, :48] @ dt_proj_w^T + b)   (4096 x 1536, K=48)
    gemm_tf32<<<dim3(DINNER / TBN, MROWS / TBM, 1), 256>>>(
        xdbl, XDBLW, dt_proj_w, DTRANK, dt, DINNER,
        MROWS, DINNER, DTRANK, dt_proj_b, 1, 0);

    // 5) q = query @ query_w^T + query_b  (4096 x 1536, K=768)
    gemm_tf32<<<dim3(DINNER / TBN, MROWS / TBM, 1), 256>>>(
        query, DMODEL, query_w, DMODEL, q, DINNER,
        MROWS, DINNER, DMODEL, query_b, 2, 0);

    // 6) chunked selective scan (ILP-optimized)
    {
        const int nblk = (DINNER / SCB) * BATCH * NCH;   // 768
        scan_phase1<<<nblk, SCB>>>(dt, xc, xdbl, A_log, aprod, hloc);
        scan_phase2<<<(NPAIRS * DSTATE) / 256, 256>>>(aprod, hloc, h0);
        scan_phase3<<<nblk, SCB>>>(dt, xc, xdbl, A_log, h0, y);
    }

    // 7) combine gates
    combine_kernel<<<elemBlocks, 256>>>(y, xc, xz, q, Dp);

    // 8) out = y @ out_proj_w^T           (4096 x 768, K=1536)
    gemm_tf32<<<dim3(DMODEL / TBN, MROWS / TBM, 1), 256>>>(
        y, DINNER, out_proj_w, DINNER, out, DMODEL,
        MROWS, DMODEL, DINNER, nullptr, 0, 0);
}

// round 11
// speedup vs baseline: 1.1441x; 1.0504x over previous
#include <cuda_runtime.h>
#include <cuda_bf16.h>
#include <math.h>
#include <stdint.h>

// ---------------- problem constants ----------------
#define BATCH   2
#define SEQLEN  2048
#define DMODEL  768
#define DINNER  1536
#define DSTATE  16
#define DCONV   4
#define DTRANK  48
#define XDBLW   (DTRANK + 2*DSTATE)   // 80
#define MROWS   (BATCH*SEQLEN)        // 4096
#define NPAIRS  (BATCH*DINNER)        // 3072
#define NCH     32
#define CHT     (SEQLEN/NCH)          // 64
#define SPLITK  8
#define XPSTRIDE ((size_t)MROWS * XDBLW)

// ---------------- scratch ----------------
__device__ float g_xz   [(size_t)MROWS * 2*DINNER];
__device__ float g_xc   [(size_t)MROWS * DINNER];
__device__ float g_xdbl [(size_t)MROWS * XDBLW];
__device__ float g_xp   [(size_t)SPLITK * MROWS * XDBLW];
__device__ float g_dt   [(size_t)MROWS * DINNER];
__device__ float g_y    [(size_t)MROWS * DINNER];
__device__ float g_q    [(size_t)MROWS * DINNER];
__device__ float g_aprod[(size_t)NPAIRS * NCH * DSTATE];
__device__ float g_hloc [(size_t)NPAIRS * NCH * DSTATE];
__device__ float g_h0   [(size_t)NPAIRS * NCH * DSTATE];

// ---------------- helpers ----------------
__device__ __forceinline__ float silu_f(float v)  { return v / (1.f + __expf(-v)); }
__device__ __forceinline__ float softplus_f(float v) { return v > 20.f ? v : log1pf(__expf(v)); }
__device__ __forceinline__ uint32_t f2tf32(float f) {
    uint32_t u; asm("cvt.rna.tf32.f32 %0, %1;" : "=r"(u) : "f"(f)); return u;
}
__device__ __forceinline__ void mma_tf32(float c[4], const uint32_t a[4], const uint32_t b[2]) {
    asm volatile(
        "mma.sync.aligned.m16n8k8.row.col.f32.tf32.tf32.f32 "
        "{%0,%1,%2,%3}, {%4,%5,%6,%7}, {%8,%9}, {%0,%1,%2,%3};\n"
        : "+f"(c[0]), "+f"(c[1]), "+f"(c[2]), "+f"(c[3])
        : "r"(a[0]), "r"(a[1]), "r"(a[2]), "r"(a[3]), "r"(b[0]), "r"(b[1]));
}
__device__ __forceinline__ int swz(int c) { return (c ^ (c >> 2)) & 31; }

// ---------------- mma.sync TF32 GEMM: C[M,N] = A[M,K] * B[N,K]^T ----------------
#define TBM 128
#define TBN 128
#define TBK 16

__global__ __launch_bounds__(256)
void gemm_tf32(const float* __restrict__ A, int lda,
               const float* __restrict__ B, int ldb,
               float* __restrict__ C, int ldc,
               int M, int N, int K,
               const float* __restrict__ bias, int epi,
               size_t splitStride)
{
    __shared__ float Af[2][2][8][128];
    __shared__ float Bf[2][2][16][64];

    const int tid  = threadIdx.x;
    const int warp = tid >> 5, lane = tid & 31;
    const int warpM = warp >> 2, warpN = warp & 3;

    const int rowBase = blockIdx.y * TBM;
    const int colBase = blockIdx.x * TBN;

    const int Ks = K / gridDim.z;
    A += (size_t)blockIdx.z * Ks;
    B += (size_t)blockIdx.z * Ks;
    C += (size_t)blockIdx.z * splitStride;

    const int lr  = tid >> 1;
    const int lks = tid & 1;
    const int lk  = lks * 8;

    const int wmi  = lr >> 4;
    const int wsel = (lr >> 3) & 1;
    const int wgid = lr & 7;
    const int wni  = lr >> 3;
    const int wbg  = lr & 7;

    float acc[4][4][4];
#pragma unroll
    for (int mi = 0; mi < 4; mi++)
#pragma unroll
        for (int ni = 0; ni < 4; ni++)
#pragma unroll
            for (int rr = 0; rr < 4; rr++) acc[mi][ni][rr] = 0.f;

    float4 pa0, pa1, pb0, pb1;
    {
        const float* ap = A + (size_t)(rowBase + lr) * lda + lk;
        pa0 = *(const float4*)(ap);
        pa1 = *(const float4*)(ap + 4);
        const int bn = colBase + lr;
        if (bn < N) {
            const float* bp = B + (size_t)bn * ldb + lk;
            pb0 = *(const float4*)(bp);
            pb1 = *(const float4*)(bp + 4);
        } else {
            pb0 = make_float4(0.f,0.f,0.f,0.f);
            pb1 = make_float4(0.f,0.f,0.f,0.f);
        }
    }

    const int ntiles = Ks / TBK;
    for (int t = 0; t < ntiles; t++) {
        const int buf = t & 1;
        {
            const float ea[8] = {pa0.x,pa0.y,pa0.z,pa0.w,pa1.x,pa1.y,pa1.z,pa1.w};
#pragma unroll
            for (int j = 0; j < 8; j++) {
                const int ch = swz(wgid * 4 + (j & 3));
                Af[buf][lks][wmi][ch * 4 + (j >> 2) * 2 + wsel] =
                    __uint_as_float(f2tf32(ea[j]));
            }
            const float eb[8] = {pb0.x,pb0.y,pb0.z,pb0.w,pb1.x,pb1.y,pb1.z,pb1.w};
#pragma unroll
            for (int j = 0; j < 4; j++) {
                const int ch = swz(wbg * 4 + j);
                Bf[buf][lks][wni][ch * 2 + 0] = __uint_as_float(f2tf32(eb[j]));
                Bf[buf][lks][wni][ch * 2 + 1] = __uint_as_float(f2tf32(eb[j + 4]));
            }
        }
        __syncthreads();

        if (t + 1 < ntiles) {
            const int k0 = (t + 1) * TBK;
            const float* apn = A + (size_t)(rowBase + lr) * lda + k0 + lk;
            pa0 = *(const float4*)(apn);
            pa1 = *(const float4*)(apn + 4);
            const int bn = colBase + lr;
            if (bn < N) {
                const float* bpn = B + (size_t)bn * ldb + k0 + lk;
                pb0 = *(const float4*)(bpn);
                pb1 = *(const float4*)(bpn + 4);
            } else {
                pb0 = make_float4(0.f,0.f,0.f,0.f);
                pb1 = make_float4(0.f,0.f,0.f,0.f);
            }
        }

#pragma unroll
        for (int ks = 0; ks < 2; ks++) {
            uint32_t af[4][4], bfr[4][2];
#pragma unroll
            for (int mi = 0; mi < 4; mi++) {
                const float4 v = *(const float4*)&Af[buf][ks][warpM*4 + mi][swz(lane)*4];
                af[mi][0] = __float_as_uint(v.x); af[mi][1] = __float_as_uint(v.y);
                af[mi][2] = __float_as_uint(v.z); af[mi][3] = __float_as_uint(v.w);
            }
#pragma unroll
            for (int ni = 0; ni < 4; ni++) {
                const float2 w = *(const float2*)&Bf[buf][ks][warpN*4 + ni][swz(lane)*2];
                bfr[ni][0] = __float_as_uint(w.x); bfr[ni][1] = __float_as_uint(w.y);
            }
#pragma unroll
            for (int mi = 0; mi < 4; mi++)
#pragma unroll
                for (int ni = 0; ni < 4; ni++)
                    mma_tf32(acc[mi][ni], af[mi], bfr[ni]);
        }
    }

    const int gid = lane >> 2, tg = lane & 3;
#pragma unroll
    for (int mi = 0; mi < 4; mi++) {
        const int r0 = rowBase + warpM * 64 + mi * 16 + gid;
#pragma unroll
        for (int ni = 0; ni < 4; ni++) {
            const int c = colBase + warpN * 32 + ni * 8 + 2 * tg;
            if (c < N) {
                float v0 = acc[mi][ni][0], v1 = acc[mi][ni][1];
                float v2 = acc[mi][ni][2], v3 = acc[mi][ni][3];
                if (epi == 1) {
                    const float b0 = bias[c], b1 = bias[c+1];
                    v0 = softplus_f(v0 + b0); v1 = softplus_f(v1 + b1);
                    v2 = softplus_f(v2 + b0); v3 = softplus_f(v3 + b1);
                } else if (epi == 2) {
                    const float b0 = bias[c], b1 = bias[c+1];
                    v0 += b0; v1 += b1; v2 += b0; v3 += b1;
                }
                *(float2*)(C + (size_t)r0       * ldc + c) = make_float2(v0, v1);
                *(float2*)(C + (size_t)(r0 + 8) * ldc + c) = make_float2(v2, v3);
            }
        }
    }
}

// ---------------- split-K reduction for x_proj ----------------
__global__ __launch_bounds__(256)
void reduce_xp(const float* __restrict__ part, float* __restrict__ xdbl)
{
    const int i = blockIdx.x * blockDim.x + threadIdx.x;
    if (i < (int)(MROWS * XDBLW)) {
        float s = part[i];
#pragma unroll
        for (int k = 1; k < SPLITK; k++) s += part[(size_t)k * XPSTRIDE + i];
        xdbl[i] = s;
    }
}

// ---------------- causal depthwise conv (width 4) + silu, sliding window ----------------
// Each thread: one channel d, 8 consecutive timesteps. 11 loads per 8 outputs.
__global__ __launch_bounds__(256)
void conv_silu_kernel(const float* __restrict__ xz,
                      const float* __restrict__ conv_w,
                      const float* __restrict__ conv_b,
                      float* __restrict__ xc)
{
    const int d  = blockIdx.x * blockDim.x + threadIdx.x;   // 0..1535
    const size_t m0 = (size_t)blockIdx.y * 8;               // global row base
    const int t0 = (int)(m0 % SEQLEN);

    const float4 cw = *(const float4*)&conv_w[d * DCONV];
    const float cb = conv_b[d];

    float w0 = 0.f, w1 = 0.f, w2 = 0.f;
    if (t0 >= 3) w0 = xz[(m0 - 3) * (2 * DINNER) + d];
    if (t0 >= 2) w1 = xz[(m0 - 2) * (2 * DINNER) + d];
    if (t0 >= 1) w2 = xz[(m0 - 1) * (2 * DINNER) + d];

#pragma unroll
    for (int j = 0; j < 8; j++) {
        const float cur = xz[(m0 + j) * (2 * DINNER) + d];
        const float v = cb + cw.x * w0 + cw.y * w1 + cw.z * w2 + cw.w * cur;
        xc[(m0 + j) * DINNER + d] = silu_f(v);
        w0 = w1; w1 = w2; w2 = cur;
    }
}

// ---------------- chunked selective scan: thread-per-channel, ILP-optimized ----------------
#define SCB 128

__global__ __launch_bounds__(SCB)
void scan_phase1(const float* __restrict__ dt,
                 const float* __restrict__ xc,
                 const float* __restrict__ xdbl,
                 const float* __restrict__ A_log,
                 float* __restrict__ aprod_g,
                 float* __restrict__ hloc_g)
{
    __shared__ float Bsh[CHT][16];
    const int tid = threadIdx.x;
    const int dg = blockIdx.x % (DINNER / SCB);
    const int b  = (blockIdx.x / (DINNER / SCB)) % BATCH;
    const int c  =  blockIdx.x / ((DINNER / SCB) * BATCH);
    const int d  = dg * SCB + tid;
    const size_t m0 = (size_t)b * SEQLEN + c * CHT;

    for (int i = tid; i < CHT * 4; i += SCB) {
        const int r = i >> 2, qq = i & 3;
        *(float4*)&Bsh[r][qq * 4] =
            *(const float4*)&xdbl[(m0 + r) * XDBLW + DTRANK + qq * 4];
    }
    __syncthreads();

    float A[16];
    {
        const float4* ap = (const float4*)&A_log[(size_t)d * DSTATE];
#pragma unroll
        for (int i = 0; i < 4; i++) {
            const float4 v = ap[i];
            A[i*4+0] = -__expf(v.x); A[i*4+1] = -__expf(v.y);
            A[i*4+2] = -__expf(v.z); A[i*4+3] = -__expf(v.w);
        }
    }
    bool fast = true;
#pragma unroll
    for (int n = 0; n < 16; n++)
        fast = fast && (fabsf(A[n] + (float)(n + 1)) <= 1e-5f * (float)(n + 1));

    float h[16];
#pragma unroll
    for (int n = 0; n < 16; n++) h[n] = 0.f;
    float ap16[16];

    if (fast) {
        float sdt = 0.f;
#pragma unroll 2
        for (int t = 0; t < CHT; t++) {
            const size_t m = m0 + t;
            const float dtv = dt[m * DINNER + d];
            const float du  = dtv * xc[m * DINNER + d];
            sdt += dtv;
            const float r1 = __expf(-dtv);
            float pw[17];
            pw[1] = r1;
#pragma unroll
            for (int n = 2; n <= 16; n++) pw[n] = pw[n >> 1] * pw[n - (n >> 1)];
#pragma unroll
            for (int n = 0; n < 16; n++)
                h[n] = pw[n + 1] * h[n] + du * Bsh[t][n];
        }
        const float rt_ = __expf(-sdt);
        float pw[17];
        pw[1] = rt_;
#pragma unroll
        for (int n = 2; n <= 16; n++) pw[n] = pw[n >> 1] * pw[n - (n >> 1)];
#pragma unroll
        for (int n = 0; n < 16; n++) ap16[n] = pw[n + 1];
    } else {
#pragma unroll
        for (int n = 0; n < 16; n++) ap16[n] = 1.f;
#pragma unroll 2
        for (int t = 0; t < CHT; t++) {
            const size_t m = m0 + t;
            const float dtv = dt[m * DINNER + d];
            const float du  = dtv * xc[m * DINNER + d];
#pragma unroll
            for (int n = 0; n < 16; n++) {
                const float a = __expf(dtv * A[n]);
                h[n] = a * h[n] + du * Bsh[t][n];
                ap16[n] *= a;
            }
        }
    }

    const int bd = b * DINNER + d;
    float* po  = &aprod_g[((size_t)bd * NCH + c) * DSTATE];
    float* phh = &hloc_g [((size_t)bd * NCH + c) * DSTATE];
#pragma unroll
    for (int i = 0; i < 4; i++) {
        *(float4*)&po[i*4]  = make_float4(ap16[i*4], ap16[i*4+1], ap16[i*4+2], ap16[i*4+3]);
        *(float4*)&phh[i*4] = make_float4(h[i*4],    h[i*4+1],    h[i*4+2],    h[i*4+3]);
    }
}

__global__ __launch_bounds__(256)
void scan_phase2(const float* __restrict__ aprod_g,
                 const float* __restrict__ hloc_g,
                 float* __restrict__ h0_g)
{
    const int idx = blockIdx.x * blockDim.x + threadIdx.x;
    const int bd = idx >> 4;
    const int n  = idx & 15;
    if (bd >= NPAIRS) return;

    float h = 0.f;
#pragma unroll
    for (int c = 0; c < NCH; c++) {
        const size_t o = ((size_t)bd * NCH + c) * DSTATE + n;
        h0_g[o] = h;
        h = aprod_g[o] * h + hloc_g[o];
    }
}

__global__ __launch_bounds__(SCB)
void scan_phase3(const float* __restrict__ dt,
                 const float* __restrict__ xc,
                 const float* __restrict__ xdbl,
                 const float* __restrict__ A_log,
                 const float* __restrict__ h0_g,
                 float* __restrict__ y)
{
    __shared__ float Bsh[CHT][16];
    __shared__ float Csh[CHT][16];
    const int tid = threadIdx.x;
    const int dg = blockIdx.x % (DINNER / SCB);
    const int b  = (blockIdx.x / (DINNER / SCB)) % BATCH;
    const int c  =  blockIdx.x / ((DINNER / SCB) * BATCH);
    const int d  = dg * SCB + tid;
    const size_t m0 = (size_t)b * SEQLEN + c * CHT;

    for (int i = tid; i < CHT * 4; i += SCB) {
        const int r = i >> 2, qq = i & 3;
        *(float4*)&Bsh[r][qq * 4] =
            *(const float4*)&xdbl[(m0 + r) * XDBLW + DTRANK + qq * 4];
        *(float4*)&Csh[r][qq * 4] =
            *(const float4*)&xdbl[(m0 + r) * XDBLW + DTRANK + DSTATE + qq * 4];
    }
    __syncthreads();

    float A[16];
    {
        const float4* ap = (const float4*)&A_log[(size_t)d * DSTATE];
#pragma unroll
        for (int i = 0; i < 4; i++) {
            const float4 v = ap[i];
            A[i*4+0] = -__expf(v.x); A[i*4+1] = -__expf(v.y);
            A[i*4+2] = -__expf(v.z); A[i*4+3] = -__expf(v.w);
        }
    }
    bool fast = true;
#pragma unroll
    for (int n = 0; n < 16; n++)
        fast = fast && (fabsf(A[n] + (float)(n + 1)) <= 1e-5f * (float)(n + 1));

    const int bd = b * DINNER + d;
    float h[16];
    {
        const float4* hp = (const float4*)&h0_g[((size_t)bd * NCH + c) * DSTATE];
#pragma unroll
        for (int i = 0; i < 4; i++) {
            const float4 v = hp[i];
            h[i*4+0] = v.x; h[i*4+1] = v.y; h[i*4+2] = v.z; h[i*4+3] = v.w;
        }
    }

    if (fast) {
#pragma unroll 2
        for (int t = 0; t < CHT; t++) {
            const size_t m = m0 + t;
            const float dtv = dt[m * DINNER + d];
            const float du  = dtv * xc[m * DINNER + d];
            const float r1  = __expf(-dtv);
            float pw[17];
            pw[1] = r1;
#pragma unroll
            for (int n = 2; n <= 16; n++) pw[n] = pw[n >> 1] * pw[n - (n >> 1)];
            float e[16];
#pragma unroll
            for (int n = 0; n < 16; n++) {
                h[n] = pw[n + 1] * h[n] + du * Bsh[t][n];
                e[n] = h[n] * Csh[t][n];
            }
#pragma unroll
            for (int st = 1; st < 16; st <<= 1)
#pragma unroll
                for (int n = 0; n < 16; n += 2 * st) e[n] += e[n + st];
            y[m * DINNER + d] = e[0];
        }
    } else {
#pragma unroll 2
        for (int t = 0; t < CHT; t++) {
            const size_t m = m0 + t;
            const float dtv = dt[m * DINNER + d];
            const float du  = dtv * xc[m * DINNER + d];
            float e[16];
#pragma unroll
            for (int n = 0; n < 16; n++) {
                const float a = __expf(dtv * A[n]);
                h[n] = a * h[n] + du * Bsh[t][n];
                e[n] = h[n] * Csh[t][n];
            }
#pragma unroll
            for (int st = 1; st < 16; st <<= 1)
#pragma unroll
                for (int n = 0; n < 16; n += 2 * st) e[n] += e[n + st];
            y[m * DINNER + d] = e[0];
        }
    }
}

// ---------------- combine (float4) ----------------
__global__ __launch_bounds__(256)
void combine_kernel(float* __restrict__ y,
                    const float* __restrict__ xc,
                    const float* __restrict__ xz,
                    const float* __restrict__ q,
                    const float* __restrict__ Dp)
{
    const int i4 = blockIdx.x * blockDim.x + threadIdx.x;
    if (i4 >= MROWS * DINNER / 4) return;
    const int m  = i4 / (DINNER / 4);
    const int d0 = (i4 % (DINNER / 4)) * 4;

    const float4 yv = *(const float4*)(y  + (size_t)i4 * 4);
    const float4 xv = *(const float4*)(xc + (size_t)i4 * 4);
    const float4 qv = *(const float4*)(q  + (size_t)i4 * 4);
    const float4 zv = *(const float4*)(xz + (size_t)m * (2 * DINNER) + DINNER + d0);
    const float4 Dv = *(const float4*)(Dp + d0);

    float4 r;
    r.x = (yv.x + xv.x * Dv.x) * silu_f(zv.x) * silu_f(qv.x);
    r.y = (yv.y + xv.y * Dv.y) * silu_f(zv.y) * silu_f(qv.y);
    r.z = (yv.z + xv.z * Dv.z) * silu_f(zv.z) * silu_f(qv.z);
    r.w = (yv.w + xv.w * Dv.w) * silu_f(zv.w) * silu_f(qv.w);
    *(float4*)(y + (size_t)i4 * 4) = r;
}

// ---------------- launch ----------------
extern "C" void kernel_launch(void* const* d_in, const int* in_sizes, int n_in,
                              void* d_out, int out_size)
{
    const float* hidden    = (const float*)d_in[0];
    const float* query     = (const float*)d_in[1];
    const float* in_proj_w = (const float*)d_in[2];
    const float* conv_w    = (const float*)d_in[3];
    const float* conv_b    = (const float*)d_in[4];
    const float* x_proj_w  = (const float*)d_in[5];
    const float* dt_proj_w = (const float*)d_in[6];
    const float* dt_proj_b = (const float*)d_in[7];
    const float* A_log     = (const float*)d_in[8];
    const float* Dp        = (const float*)d_in[9];
    const float* query_w   = (const float*)d_in[10];
    const float* query_b   = (const float*)d_in[11];
    const float* out_proj_w= (const float*)d_in[12];
    float* out = (float*)d_out;

    float *xz, *xc, *xdbl, *xp, *dt, *y, *q, *aprod, *hloc, *h0;
    cudaGetSymbolAddress((void**)&xz,    g_xz);
    cudaGetSymbolAddress((void**)&xc,    g_xc);
    cudaGetSymbolAddress((void**)&xdbl,  g_xdbl);
    cudaGetSymbolAddress((void**)&xp,    g_xp);
    cudaGetSymbolAddress((void**)&dt,    g_dt);
    cudaGetSymbolAddress((void**)&y,     g_y);
    cudaGetSymbolAddress((void**)&q,     g_q);
    cudaGetSymbolAddress((void**)&aprod, g_aprod);
    cudaGetSymbolAddress((void**)&hloc,  g_hloc);
    cudaGetSymbolAddress((void**)&h0,    g_h0);

    // 1) xz = hidden @ in_proj_w^T        (4096 x 3072, K=768)
    gemm_tf32<<<dim3(2 * DINNER / TBN, MROWS / TBM, 1), 256>>>(
        hidden, DMODEL, in_proj_w, DMODEL, xz, 2 * DINNER,
        MROWS, 2 * DINNER, DMODEL, nullptr, 0, 0);

    // 2) q = query @ query_w^T + query_b  (4096 x 1536, K=768) -- independent, early
    gemm_tf32<<<dim3(DINNER / TBN, MROWS / TBM, 1), 256>>>(
        query, DMODEL, query_w, DMODEL, q, DINNER,
        MROWS, DINNER, DMODEL, query_b, 2, 0);

    // 3) causal conv + silu (sliding window)
    conv_silu_kernel<<<dim3(DINNER / 256, MROWS / 8), 256>>>(xz, conv_w, conv_b, xc);

    // 4) x_dbl = xc @ x_proj_w^T          (4096 x 80, K=1536) split-K=8
    gemm_tf32<<<dim3(1, MROWS / TBM, SPLITK), 256>>>(
        xc, DINNER, x_proj_w, DINNER, xp, XDBLW,
        MROWS, XDBLW, DINNER, nullptr, 0, XPSTRIDE);
    reduce_xp<<<(MROWS * XDBLW + 255) / 256, 256>>>(xp, xdbl);

    // 5) dt = softplus(x_dbl[:, :48] @ dt_proj_w^T + b)   (4096 x 1536, K=48)
    gemm_tf32<<<dim3(DINNER / TBN, MROWS / TBM, 1), 256>>>(
        xdbl, XDBLW, dt_proj_w, DTRANK, dt, DINNER,
        MROWS, DINNER, DTRANK, dt_proj_b, 1, 0);

    // 6) chunked selective scan (ILP-optimized)
    {
        const int nblk = (DINNER / SCB) * BATCH * NCH;   // 768
        scan_phase1<<<nblk, SCB>>>(dt, xc, xdbl, A_log, aprod, hloc);
        scan_phase2<<<(NPAIRS * DSTATE) / 256, 256>>>(aprod, hloc, h0);
        scan_phase3<<<nblk, SCB>>>(dt, xc, xdbl, A_log, h0, y);
    }

    // 7) combine gates (float4)
    combine_kernel<<<(MROWS * DINNER / 4 + 255) / 256, 256>>>(y, xc, xz, q, Dp);

    // 8) out = y @ out_proj_w^T           (4096 x 768, K=1536)
    gemm_tf32<<<dim3(DMODEL / TBN, MROWS / TBM, 1), 256>>>(
        y, DINNER, out_proj_w, DINNER, out, DMODEL,
        MROWS, DMODEL, DINNER, nullptr, 0, 0);
}